// round 3
// baseline (speedup 1.0000x reference)
#include <cuda_runtime.h>

#define NG 1024
#define R0 8192
#define C0 4096
#define R1 4096
#define C1 2048
#define RM 512

#define A_BLOCKS 4096          // 1024 groups x 4 column tiles
#define P1_BLOCKS 512          // 4096 rows, one warp per row
#define C_BLOCKS 16
#define B_BLOCKS 64            // 512 rows, one warp per row

// Scratch (device globals — no allocation allowed)
__device__ int    g_off[NG + 1];
__device__ int    g_rows[R0];
__device__ float  g_p2[C0];
__device__ float  g_p1[R1];
__device__ double g_loss[3];
__device__ int    g_done;

__device__ __forceinline__ float block_reduce256(float v, float* sh) {
    int t = threadIdx.x;
    #pragma unroll
    for (int o = 16; o; o >>= 1) v += __shfl_down_sync(0xffffffffu, v, o);
    if ((t & 31) == 0) sh[t >> 5] = v;
    __syncthreads();
    if (t < 8) {
        v = sh[t];
        #pragma unroll
        for (int o = 4; o; o >>= 1) v += __shfl_down_sync(0x000000ffu, v, o);
    }
    return v; // valid in thread 0
}

// ---------------------------------------------------------------------------
// One-block prologue: width-detect idx0, build CSR (count/scan/fill) in smem,
// zero all global scratch. Replaces 5 micro-kernels.
// ---------------------------------------------------------------------------
__global__ __launch_bounds__(1024) void k_prep(const unsigned int* __restrict__ idx_raw) {
    __shared__ int sidx[R0];        // 32 KB
    __shared__ int sa[NG];          // 4 KB (scan ping)
    __shared__ int sb[NG];          // 4 KB (scan pong / cursor)
    __shared__ int sflag;
    int t = threadIdx.x;

    if (t == 0) sflag = 1;
    sa[t] = 0;
    __syncthreads();

    // int64 vs int32 detection: for int64 (values < 1024) all odd dwords are 0.
    int odd = 0;
    for (int i = t; i < R0 / 2; i += 1024) odd |= (idx_raw[2 * i + 1] != 0u);
    if (odd) atomicExch(&sflag, 0);
    __syncthreads();
    int is64 = sflag;

    if (is64) {
        const long long* p = (const long long*)idx_raw;
        for (int i = t; i < R0; i += 1024) sidx[i] = (int)p[i];
    } else {
        const int* p = (const int*)idx_raw;
        for (int i = t; i < R0; i += 1024) sidx[i] = p[i];
    }
    __syncthreads();

    for (int i = t; i < R0; i += 1024) atomicAdd(&sa[sidx[i]], 1);
    __syncthreads();

    int mine = sa[t];
    // Hillis-Steele inclusive scan, ping-pong buffers
    int* a = sa; int* b = sb;
    for (int d = 1; d < NG; d <<= 1) {
        b[t] = a[t] + ((t >= d) ? a[t - d] : 0);
        __syncthreads();
        int* tmp = a; a = b; b = tmp;
    }
    int incl = a[t];
    int excl = incl - mine;
    g_off[t] = excl;
    if (t == NG - 1) g_off[NG] = incl;
    b[t] = excl;                    // cursor
    __syncthreads();

    for (int i = t; i < R0; i += 1024) {
        int g = sidx[i];
        int p = atomicAdd(&b[g], 1);
        g_rows[p] = i;
    }

    for (int i = t; i < C0; i += 1024) g_p2[i] = 0.f;
    if (t < 3) g_loss[t] = 0.0;
    if (t == 0) g_done = 0;
}

// ---------------------------------------------------------------------------
// Main fused kernel: obs-A (segment sum + loss_a + p2 fold) and p1 rowsums.
// ---------------------------------------------------------------------------
__global__ __launch_bounds__(256) void k_main(const float* __restrict__ theta0,
                                              const float* __restrict__ obs0,
                                              const float* __restrict__ theta1) {
    int bx = blockIdx.x;
    if (bx < A_BLOCKS) {
        __shared__ int srows[64];
        __shared__ float sh[8];
        int g = bx >> 2;
        int c = ((bx & 3) * 256 + threadIdx.x) * 4;
        int base = __ldg(&g_off[g]);
        int cnt  = __ldg(&g_off[g + 1]) - base;
        for (int j = threadIdx.x; j < cnt; j += 256) srows[j] = g_rows[base + j];
        // load obs0 early (overlaps with gather)
        float4 o = *(const float4*)(obs0 + (size_t)g * C0 + c);
        __syncthreads();

        float ax = 0.f, ay = 0.f, az = 0.f, aw = 0.f;
        int j = 0;
        for (; j + 4 <= cnt; j += 4) {   // MLP=4: four independent loads in flight
            float4 v0 = *(const float4*)(theta0 + (size_t)srows[j]     * C0 + c);
            float4 v1 = *(const float4*)(theta0 + (size_t)srows[j + 1] * C0 + c);
            float4 v2 = *(const float4*)(theta0 + (size_t)srows[j + 2] * C0 + c);
            float4 v3 = *(const float4*)(theta0 + (size_t)srows[j + 3] * C0 + c);
            ax += __expf(v0.x) + __expf(v1.x) + __expf(v2.x) + __expf(v3.x);
            ay += __expf(v0.y) + __expf(v1.y) + __expf(v2.y) + __expf(v3.y);
            az += __expf(v0.z) + __expf(v1.z) + __expf(v2.z) + __expf(v3.z);
            aw += __expf(v0.w) + __expf(v1.w) + __expf(v2.w) + __expf(v3.w);
        }
        for (; j < cnt; j++) {
            float4 v = *(const float4*)(theta0 + (size_t)srows[j] * C0 + c);
            ax += __expf(v.x); ay += __expf(v.y);
            az += __expf(v.z); aw += __expf(v.w);
        }
        atomicAdd(&g_p2[c + 0], ax);
        atomicAdd(&g_p2[c + 1], ay);
        atomicAdd(&g_p2[c + 2], az);
        atomicAdd(&g_p2[c + 3], aw);

        float dx = o.x - ax, dy = o.y - ay, dz = o.z - az, dw = o.w - aw;
        float v = dx * dx + dy * dy + dz * dz + dw * dw;
        v = block_reduce256(v, sh);
        if (threadIdx.x == 0) atomicAdd(&g_loss[0], (double)v);
    } else {
        // p1 rowsum-of-exp: one warp per theta1 row
        int gid = (bx - A_BLOCKS) * 256 + threadIdx.x;
        int w = gid >> 5, lane = gid & 31;
        const float4* row = (const float4*)(theta1 + (size_t)w * C1);
        float s = 0.f;
        #pragma unroll 4
        for (int j = lane; j < C1 / 4; j += 32) {
            float4 v = row[j];
            s += __expf(v.x) + __expf(v.y) + __expf(v.z) + __expf(v.w);
        }
        #pragma unroll
        for (int o = 16; o; o >>= 1) s += __shfl_down_sync(0xffffffffu, s, o);
        if (lane == 0) g_p1[w] = s;
    }
}

// ---------------------------------------------------------------------------
// Epilogue: obs-C + obs-B, with done-counter: the last block writes the output.
// ---------------------------------------------------------------------------
__global__ __launch_bounds__(256) void k_post(const float* __restrict__ obs2,
                                              const float* __restrict__ mapping1,
                                              const float* __restrict__ obs1,
                                              float* __restrict__ out) {
    __shared__ float sh[8];
    int bx = blockIdx.x;
    if (bx < C_BLOCKS) {
        int c = bx * 256 + threadIdx.x;
        float d = obs2[c] - g_p2[c];
        float v = block_reduce256(d * d, sh);
        if (threadIdx.x == 0) atomicAdd(&g_loss[2], (double)v);
    } else {
        int gid = (bx - C_BLOCKS) * 256 + threadIdx.x;
        int w = gid >> 5, lane = gid & 31;
        const float4* row = (const float4*)(mapping1 + (size_t)w * C0);
        const float4* p = (const float4*)g_p1;
        float s = 0.f;
        #pragma unroll 4
        for (int j = lane; j < C0 / 4; j += 32) {
            float4 m = row[j];
            float4 q = p[j];
            s += m.x * q.x + m.y * q.y + m.z * q.z + m.w * q.w;
        }
        #pragma unroll
        for (int o = 16; o; o >>= 1) s += __shfl_down_sync(0xffffffffu, s, o);
        if (lane == 0) {
            double d = (double)obs1[w] - (double)s;
            atomicAdd(&g_loss[1], d * d);
        }
    }
    __syncthreads();
    __threadfence();
    if (threadIdx.x == 0) {
        int done = atomicAdd(&g_done, 1);
        if (done == (int)gridDim.x - 1) {
            __threadfence();
            double la = *(volatile double*)&g_loss[0];
            double lb = *(volatile double*)&g_loss[1];
            double lc = *(volatile double*)&g_loss[2];
            la /= (double)((size_t)NG * (size_t)C0);
            lb /= (double)RM;
            lc = 0.5 * lc / (double)C0;
            out[0] = (float)((la + lb + lc) / 3.0);
        }
    }
}

extern "C" void kernel_launch(void* const* d_in, const int* in_sizes, int n_in,
                              void* d_out, int out_size) {
    const float* theta0   = (const float*)d_in[0];
    const float* theta1   = (const float*)d_in[1];
    const float* obs0     = (const float*)d_in[2];
    const float* obs1     = (const float*)d_in[3];
    const float* obs2     = (const float*)d_in[4];
    const void*  idx0     = d_in[5];
    const float* mapping1 = (const float*)d_in[6];
    float* out = (float*)d_out;

    k_prep<<<1, 1024>>>((const unsigned int*)idx0);
    k_main<<<A_BLOCKS + P1_BLOCKS, 256>>>(theta0, obs0, theta1);
    k_post<<<C_BLOCKS + B_BLOCKS, 256>>>(obs2, mapping1, obs1, out);
}

// round 5
// speedup vs baseline: 1.9523x; 1.9523x over previous
#include <cuda_runtime.h>

#define NG 1024
#define R0 8192
#define C0 4096
#define R1 4096
#define C1 2048
#define RM 512

#define GPB 8                   // groups per obsA block
#define A_BLOCKS 512            // (1024/8 group-sets) x (4096/1024 col tiles)
#define P1_BLOCKS 512           // 4096 rows, one warp per row
#define C_BLOCKS 16
#define B_BLOCKS 64             // 512 rows, one warp per row
#define LCAP 256                // per-group row list capacity (mean cnt = 8)

// Scratch (device globals — zero at process start; every call restores the
// accumulators to zero before finishing, so no zero-prologue kernel).
__device__ float  g_p2[C0];
__device__ float  g_p1[R1];
__device__ double g_loss[3];
__device__ int    g_done;

__device__ __forceinline__ float block_reduce256(float v, float* sh) {
    int t = threadIdx.x;
    #pragma unroll
    for (int o = 16; o; o >>= 1) v += __shfl_down_sync(0xffffffffu, v, o);
    if ((t & 31) == 0) sh[t >> 5] = v;
    __syncthreads();
    if (t < 8) {
        v = sh[t];
        #pragma unroll
        for (int o = 4; o; o >>= 1) v += __shfl_down_sync(0x000000ffu, v, o);
    }
    return v; // valid in thread 0
}

// ---------------------------------------------------------------------------
// Main fused kernel.
//  blocks [0, A_BLOCKS): obs-A. Each block owns 8 groups x 1024 columns.
//    It scans the (L2-resident) idx vector to build its own 8 row lists —
//    no global CSR, no prologue. Segment sums live in registers; loss_a is
//    computed in place; p2 partials fold with ONE float atomic per column.
//  blocks [A_BLOCKS, +P1_BLOCKS): p1 = rowsum of exp(theta1), warp per row.
// ---------------------------------------------------------------------------
__global__ __launch_bounds__(256) void k_main(const float* __restrict__ theta0,
                                              const float* __restrict__ obs0,
                                              const float* __restrict__ theta1,
                                              const unsigned int* __restrict__ idx_raw) {
    int bx = blockIdx.x;
    if (bx < A_BLOCKS) {
        __shared__ int   scnt[GPB];
        __shared__ short slist[GPB * LCAP];
        __shared__ float sh[8];
        int t = threadIdx.x;
        int gset = bx >> 2;             // 0..127
        int tile = bx & 3;              // 0..3
        int g0 = gset * GPB;
        int c = tile * 1024 + t * 4;

        if (t < GPB) scnt[t] = 0;
        __syncthreads();

        // int64 vs int32 width detection: for int64 values < 1024 every odd
        // 32-bit word is zero; for int32 odd words are random group ids
        // (all-zero over 1024 samples has probability ~0).
        unsigned int hi = 0;
        #pragma unroll
        for (int s = 0; s < 4; s++) hi |= idx_raw[2 * (t + 256 * s) + 1];
        int is32 = __syncthreads_or(hi != 0u);

        // Scan idx, collect rows belonging to our 8 groups.
        if (is32) {
            const int* p = (const int*)idx_raw;
            #pragma unroll 4
            for (int i = t; i < R0; i += 256) {
                int g = p[i] - g0;
                if ((unsigned)g < GPB) {
                    int s = atomicAdd(&scnt[g], 1);
                    if (s < LCAP) slist[g * LCAP + s] = (short)i;
                }
            }
        } else {
            const long long* p = (const long long*)idx_raw;
            #pragma unroll 4
            for (int i = t; i < R0; i += 256) {
                int g = (int)p[i] - g0;
                if ((unsigned)g < GPB) {
                    int s = atomicAdd(&scnt[g], 1);
                    if (s < LCAP) slist[g * LCAP + s] = (short)i;
                }
            }
        }
        __syncthreads();

        float px = 0.f, py = 0.f, pz = 0.f, pw = 0.f;   // p2 partial (8 groups)
        float lsum = 0.f;                                // loss_a partial
        #pragma unroll 1
        for (int gg = 0; gg < GPB; gg++) {
            int cnt = scnt[gg];
            const short* rows = &slist[gg * LCAP];
            float ax = 0.f, ay = 0.f, az = 0.f, aw = 0.f;
            int j = 0;
            for (; j + 4 <= cnt; j += 4) {   // MLP=4
                int r0 = rows[j], r1 = rows[j + 1], r2 = rows[j + 2], r3 = rows[j + 3];
                float4 v0 = *(const float4*)(theta0 + (size_t)(unsigned short)r0 * C0 + c);
                float4 v1 = *(const float4*)(theta0 + (size_t)(unsigned short)r1 * C0 + c);
                float4 v2 = *(const float4*)(theta0 + (size_t)(unsigned short)r2 * C0 + c);
                float4 v3 = *(const float4*)(theta0 + (size_t)(unsigned short)r3 * C0 + c);
                ax += __expf(v0.x) + __expf(v1.x) + __expf(v2.x) + __expf(v3.x);
                ay += __expf(v0.y) + __expf(v1.y) + __expf(v2.y) + __expf(v3.y);
                az += __expf(v0.z) + __expf(v1.z) + __expf(v2.z) + __expf(v3.z);
                aw += __expf(v0.w) + __expf(v1.w) + __expf(v2.w) + __expf(v3.w);
            }
            for (; j < cnt; j++) {
                float4 v = *(const float4*)(theta0 + (size_t)(unsigned short)rows[j] * C0 + c);
                ax += __expf(v.x); ay += __expf(v.y);
                az += __expf(v.z); aw += __expf(v.w);
            }
            px += ax; py += ay; pz += az; pw += aw;
            float4 o = *(const float4*)(obs0 + (size_t)(g0 + gg) * C0 + c);
            float dx = o.x - ax, dy = o.y - ay, dz = o.z - az, dw = o.w - aw;
            lsum += dx * dx + dy * dy + dz * dz + dw * dw;
        }

        atomicAdd(&g_p2[c + 0], px);
        atomicAdd(&g_p2[c + 1], py);
        atomicAdd(&g_p2[c + 2], pz);
        atomicAdd(&g_p2[c + 3], pw);

        float v = block_reduce256(lsum, sh);
        if (threadIdx.x == 0) atomicAdd(&g_loss[0], (double)v);
    } else {
        // p1 rowsum-of-exp: one warp per theta1 row
        int gid = (bx - A_BLOCKS) * 256 + threadIdx.x;
        int w = gid >> 5, lane = gid & 31;
        const float4* row = (const float4*)(theta1 + (size_t)w * C1);
        float s = 0.f;
        #pragma unroll 4
        for (int j = lane; j < C1 / 4; j += 32) {
            float4 v = row[j];
            s += __expf(v.x) + __expf(v.y) + __expf(v.z) + __expf(v.w);
        }
        #pragma unroll
        for (int o = 16; o; o >>= 1) s += __shfl_down_sync(0xffffffffu, s, o);
        if (lane == 0) g_p1[w] = s;
    }
}

// ---------------------------------------------------------------------------
// Epilogue: obs-C + obs-B. The last block writes the output; accumulators are
// restored to zero for the next (graph-replayed) call. g_p1 needs no restore:
// k_main fully overwrites it every call.
// ---------------------------------------------------------------------------
__global__ __launch_bounds__(256) void k_post(const float* __restrict__ obs2,
                                              const float* __restrict__ mapping1,
                                              const float* __restrict__ obs1,
                                              float* __restrict__ out) {
    __shared__ float sh[8];
    int bx = blockIdx.x;
    if (bx < C_BLOCKS) {
        int c = bx * 256 + threadIdx.x;
        float d = obs2[c] - g_p2[c];
        g_p2[c] = 0.f;                      // restore for next call
        float v = block_reduce256(d * d, sh);
        if (threadIdx.x == 0) atomicAdd(&g_loss[2], (double)v);
    } else {
        int gid = (bx - C_BLOCKS) * 256 + threadIdx.x;
        int w = gid >> 5, lane = gid & 31;
        const float4* row = (const float4*)(mapping1 + (size_t)w * C0);
        const float4* p = (const float4*)g_p1;
        float s = 0.f;
        #pragma unroll 4
        for (int j = lane; j < C0 / 4; j += 32) {
            float4 m = row[j];
            float4 q = p[j];
            s += m.x * q.x + m.y * q.y + m.z * q.z + m.w * q.w;
        }
        #pragma unroll
        for (int o = 16; o; o >>= 1) s += __shfl_down_sync(0xffffffffu, s, o);
        if (lane == 0) {
            double d = (double)obs1[w] - (double)s;
            atomicAdd(&g_loss[1], d * d);
        }
    }
    __syncthreads();
    __threadfence();
    if (threadIdx.x == 0) {
        int done = atomicAdd(&g_done, 1);
        if (done == (int)gridDim.x - 1) {
            __threadfence();
            double la = *(volatile double*)&g_loss[0];
            double lb = *(volatile double*)&g_loss[1];
            double lc = *(volatile double*)&g_loss[2];
            la /= (double)((size_t)NG * (size_t)C0);
            lb /= (double)RM;
            lc = 0.5 * lc / (double)C0;
            out[0] = (float)((la + lb + lc) / 3.0);
            // restore accumulators for the next call
            g_loss[0] = 0.0; g_loss[1] = 0.0; g_loss[2] = 0.0;
            g_done = 0;
        }
    }
}

extern "C" void kernel_launch(void* const* d_in, const int* in_sizes, int n_in,
                              void* d_out, int out_size) {
    const float* theta0   = (const float*)d_in[0];
    const float* theta1   = (const float*)d_in[1];
    const float* obs0     = (const float*)d_in[2];
    const float* obs1     = (const float*)d_in[3];
    const float* obs2     = (const float*)d_in[4];
    const void*  idx0     = d_in[5];
    const float* mapping1 = (const float*)d_in[6];
    float* out = (float*)d_out;

    k_main<<<A_BLOCKS + P1_BLOCKS, 256>>>(theta0, obs0, theta1,
                                          (const unsigned int*)idx0);
    k_post<<<C_BLOCKS + B_BLOCKS, 256>>>(obs2, mapping1, obs1, out);
}

// round 6
// speedup vs baseline: 2.1420x; 1.0971x over previous
#include <cuda_runtime.h>

#define NG 1024
#define R0 8192
#define C0 4096
#define R1 4096
#define C1 2048
#define RM 512

#define GPB 8                   // groups per obsA block
#define A_BLOCKS 512            // (1024/8 group-sets) x (4096/1024 col tiles)
#define P1_BLOCKS 512           // 4096 rows, one warp per row
#define C_BLOCKS 16
#define B_BLOCKS RM             // one block per mapping row
#define LCAP 256                // per-group row list capacity (mean cnt = 8)

// Scratch (device globals — zero at process start; every call restores the
// accumulators to zero before finishing, so no zero-prologue kernel).
__device__ float  g_p2[C0];
__device__ float  g_p1[R1];
__device__ double g_loss[3];
__device__ int    g_done;

__device__ __forceinline__ float block_reduce256(float v, float* sh) {
    int t = threadIdx.x;
    #pragma unroll
    for (int o = 16; o; o >>= 1) v += __shfl_down_sync(0xffffffffu, v, o);
    if ((t & 31) == 0) sh[t >> 5] = v;
    __syncthreads();
    if (t < 8) {
        v = sh[t];
        #pragma unroll
        for (int o = 4; o; o >>= 1) v += __shfl_down_sync(0x000000ffu, v, o);
    }
    return v; // valid in thread 0
}

// ---------------------------------------------------------------------------
// Main fused kernel.
//  blocks [0, A_BLOCKS): obs-A. Each block owns 8 groups x 1024 columns.
//    It scans the (L2-resident) idx vector to build its own 8 row lists —
//    no global CSR, no prologue. Segment sums live in registers; loss_a is
//    computed in place; p2 partials fold with ONE float atomic per column.
//  blocks [A_BLOCKS, +P1_BLOCKS): p1 = rowsum of exp(theta1), warp per row.
// ---------------------------------------------------------------------------
__global__ __launch_bounds__(256) void k_main(const float* __restrict__ theta0,
                                              const float* __restrict__ obs0,
                                              const float* __restrict__ theta1,
                                              const unsigned int* __restrict__ idx_raw) {
    int bx = blockIdx.x;
    if (bx < A_BLOCKS) {
        __shared__ int   scnt[GPB];
        __shared__ short slist[GPB * LCAP];
        __shared__ float sh[8];
        int t = threadIdx.x;
        int gset = bx >> 2;             // 0..127
        int tile = bx & 3;              // 0..3
        int g0 = gset * GPB;
        int c = tile * 1024 + t * 4;

        if (t < GPB) scnt[t] = 0;
        __syncthreads();

        // int64 vs int32 width detection: for int64 values < 1024 every odd
        // 32-bit word is zero; for int32 odd words are random group ids
        // (all-zero over 1024 samples has probability ~0).
        unsigned int hi = 0;
        #pragma unroll
        for (int s = 0; s < 4; s++) hi |= idx_raw[2 * (t + 256 * s) + 1];
        int is32 = __syncthreads_or(hi != 0u);

        // Scan idx, collect rows belonging to our 8 groups.
        if (is32) {
            const int* p = (const int*)idx_raw;
            #pragma unroll 4
            for (int i = t; i < R0; i += 256) {
                int g = p[i] - g0;
                if ((unsigned)g < GPB) {
                    int s = atomicAdd(&scnt[g], 1);
                    if (s < LCAP) slist[g * LCAP + s] = (short)i;
                }
            }
        } else {
            const long long* p = (const long long*)idx_raw;
            #pragma unroll 4
            for (int i = t; i < R0; i += 256) {
                int g = (int)p[i] - g0;
                if ((unsigned)g < GPB) {
                    int s = atomicAdd(&scnt[g], 1);
                    if (s < LCAP) slist[g * LCAP + s] = (short)i;
                }
            }
        }
        __syncthreads();

        float px = 0.f, py = 0.f, pz = 0.f, pw = 0.f;   // p2 partial (8 groups)
        float lsum = 0.f;                                // loss_a partial
        #pragma unroll 1
        for (int gg = 0; gg < GPB; gg++) {
            int cnt = scnt[gg];
            const short* rows = &slist[gg * LCAP];
            float ax = 0.f, ay = 0.f, az = 0.f, aw = 0.f;
            int j = 0;
            for (; j + 4 <= cnt; j += 4) {   // MLP=4
                int r0 = rows[j], r1 = rows[j + 1], r2 = rows[j + 2], r3 = rows[j + 3];
                float4 v0 = *(const float4*)(theta0 + (size_t)(unsigned short)r0 * C0 + c);
                float4 v1 = *(const float4*)(theta0 + (size_t)(unsigned short)r1 * C0 + c);
                float4 v2 = *(const float4*)(theta0 + (size_t)(unsigned short)r2 * C0 + c);
                float4 v3 = *(const float4*)(theta0 + (size_t)(unsigned short)r3 * C0 + c);
                ax += __expf(v0.x) + __expf(v1.x) + __expf(v2.x) + __expf(v3.x);
                ay += __expf(v0.y) + __expf(v1.y) + __expf(v2.y) + __expf(v3.y);
                az += __expf(v0.z) + __expf(v1.z) + __expf(v2.z) + __expf(v3.z);
                aw += __expf(v0.w) + __expf(v1.w) + __expf(v2.w) + __expf(v3.w);
            }
            for (; j < cnt; j++) {
                float4 v = *(const float4*)(theta0 + (size_t)(unsigned short)rows[j] * C0 + c);
                ax += __expf(v.x); ay += __expf(v.y);
                az += __expf(v.z); aw += __expf(v.w);
            }
            px += ax; py += ay; pz += az; pw += aw;
            float4 o = *(const float4*)(obs0 + (size_t)(g0 + gg) * C0 + c);
            float dx = o.x - ax, dy = o.y - ay, dz = o.z - az, dw = o.w - aw;
            lsum += dx * dx + dy * dy + dz * dz + dw * dw;
        }

        atomicAdd(&g_p2[c + 0], px);
        atomicAdd(&g_p2[c + 1], py);
        atomicAdd(&g_p2[c + 2], pz);
        atomicAdd(&g_p2[c + 3], pw);

        float v = block_reduce256(lsum, sh);
        if (threadIdx.x == 0) atomicAdd(&g_loss[0], (double)v);
    } else {
        // p1 rowsum-of-exp: one warp per theta1 row
        int gid = (bx - A_BLOCKS) * 256 + threadIdx.x;
        int w = gid >> 5, lane = gid & 31;
        const float4* row = (const float4*)(theta1 + (size_t)w * C1);
        float s = 0.f;
        #pragma unroll 4
        for (int j = lane; j < C1 / 4; j += 32) {
            float4 v = row[j];
            s += __expf(v.x) + __expf(v.y) + __expf(v.z) + __expf(v.w);
        }
        #pragma unroll
        for (int o = 16; o; o >>= 1) s += __shfl_down_sync(0xffffffffu, s, o);
        if (lane == 0) g_p1[w] = s;
    }
}

// ---------------------------------------------------------------------------
// Epilogue.
//  blocks [0, C_BLOCKS): obs-C (p2 vs obs2) + restore g_p2 to zero.
//  blocks [C_BLOCKS, +B_BLOCKS): obs-B — ONE BLOCK PER mapping1 ROW
//    (512 blocks; each thread owns 4 float4 of the 4096-dot; p1 is 16 KB,
//    L1/L2-resident). Last block computes the output and restores the
//    accumulators for the next graph replay.
// ---------------------------------------------------------------------------
__global__ __launch_bounds__(256) void k_post(const float* __restrict__ obs2,
                                              const float* __restrict__ mapping1,
                                              const float* __restrict__ obs1,
                                              float* __restrict__ out) {
    __shared__ float sh[8];
    int bx = blockIdx.x;
    int t = threadIdx.x;
    if (bx < C_BLOCKS) {
        int c = bx * 256 + t;
        float d = obs2[c] - g_p2[c];
        g_p2[c] = 0.f;                      // restore for next call
        float v = block_reduce256(d * d, sh);
        if (t == 0) atomicAdd(&g_loss[2], (double)v);
    } else {
        int w = bx - C_BLOCKS;              // output row 0..511
        const float4* row = (const float4*)(mapping1 + (size_t)w * C0);
        const float4* p = (const float4*)g_p1;
        float s = 0.f;
        #pragma unroll
        for (int j = 0; j < 4; j++) {       // 4 independent float4 pairs
            int k = t + j * 256;
            float4 m = row[k];
            float4 q = p[k];
            s += m.x * q.x + m.y * q.y + m.z * q.z + m.w * q.w;
        }
        float v = block_reduce256(s, sh);
        if (t == 0) {
            double d = (double)obs1[w] - (double)v;
            atomicAdd(&g_loss[1], d * d);
        }
    }
    __syncthreads();
    __threadfence();
    if (t == 0) {
        int done = atomicAdd(&g_done, 1);
        if (done == (int)gridDim.x - 1) {
            __threadfence();
            double la = *(volatile double*)&g_loss[0];
            double lb = *(volatile double*)&g_loss[1];
            double lc = *(volatile double*)&g_loss[2];
            la /= (double)((size_t)NG * (size_t)C0);
            lb /= (double)RM;
            lc = 0.5 * lc / (double)C0;
            out[0] = (float)((la + lb + lc) / 3.0);
            // restore accumulators for the next call
            g_loss[0] = 0.0; g_loss[1] = 0.0; g_loss[2] = 0.0;
            g_done = 0;
        }
    }
}

extern "C" void kernel_launch(void* const* d_in, const int* in_sizes, int n_in,
                              void* d_out, int out_size) {
    const float* theta0   = (const float*)d_in[0];
    const float* theta1   = (const float*)d_in[1];
    const float* obs0     = (const float*)d_in[2];
    const float* obs1     = (const float*)d_in[3];
    const float* obs2     = (const float*)d_in[4];
    const void*  idx0     = d_in[5];
    const float* mapping1 = (const float*)d_in[6];
    float* out = (float*)d_out;

    k_main<<<A_BLOCKS + P1_BLOCKS, 256>>>(theta0, obs0, theta1,
                                          (const unsigned int*)idx0);
    k_post<<<C_BLOCKS + B_BLOCKS, 256>>>(obs2, mapping1, obs1, out);
}

// round 8
// speedup vs baseline: 2.3306x; 1.0881x over previous
#include <cuda_runtime.h>

#define NG 1024
#define R0 8192
#define C0 4096
#define R1 4096
#define C1 2048
#define RM 512

#define GPB 8                   // groups per obsA block
#define A_BLOCKS 512            // (1024/8 group-sets) x (4096/1024 col tiles)
#define P1_BLOCKS 512           // theta1 rows / 8 rows-per-block
#define C_BLOCKS 16
#define B_ROWS_PER_BLOCK 4
#define B_BLOCKS (RM / B_ROWS_PER_BLOCK)   // 128
#define LCAP 256                // per-group row list capacity (mean cnt = 8)
#define FCAP 1024               // flat list capacity (actual total ~64)

// Scratch (device globals — zero at process start; accumulators restored to
// zero at the end of every call, so no zero-prologue kernel).
__device__ float  g_p2[C0];
__device__ float  g_p1[R1];
__device__ double g_loss[3];
__device__ int    g_done;

__device__ __forceinline__ float block_reduce256(float v, float* sh) {
    int t = threadIdx.x;
    #pragma unroll
    for (int o = 16; o; o >>= 1) v += __shfl_down_sync(0xffffffffu, v, o);
    if ((t & 31) == 0) sh[t >> 5] = v;
    __syncthreads();
    if (t < 8) {
        v = sh[t];
        #pragma unroll
        for (int o = 4; o; o >>= 1) v += __shfl_down_sync(0x000000ffu, v, o);
    }
    return v; // valid in thread 0
}

// ---------------------------------------------------------------------------
// Main fused kernel. A-blocks and P1-blocks interleaved by bid parity.
//  A-block: 8 groups x 1024 columns. Builds its own row lists from the
//    L2-resident idx vector, compacts them into one flat ordered list, then
//    streams it in 8-row chunks with all 8 loads in flight (uniform MLP=8).
//    Group boundaries flushed inline (block-uniform -> no divergence).
//  P1-block: 8 rows of theta1, rowsum of exp, one warp per row.
// ---------------------------------------------------------------------------
__global__ __launch_bounds__(256) void k_main(const float* __restrict__ theta0,
                                              const float* __restrict__ obs0,
                                              const float* __restrict__ theta1,
                                              const unsigned int* __restrict__ idx_raw) {
    int bx = blockIdx.x;
    if ((bx & 1) == 0) {
        // ----------------- obs-A -----------------
        int ab = bx >> 1;               // 0..511
        __shared__ int   scnt[GPB];
        __shared__ short slist[GPB * LCAP];
        __shared__ short sflat[FCAP];
        __shared__ float sh[8];
        int t = threadIdx.x;
        int gset = ab >> 2;             // 0..127
        int tile = ab & 3;              // 0..3
        int g0 = gset * GPB;
        int c = tile * 1024 + t * 4;

        if (t < GPB) scnt[t] = 0;
        __syncthreads();

        // int64 vs int32 width detection: for int64 values < 1024 every odd
        // 32-bit word is zero; for int32 odd words are random group ids.
        unsigned int hi = 0;
        #pragma unroll
        for (int s = 0; s < 4; s++) hi |= idx_raw[2 * (t + 256 * s) + 1];
        int is32 = __syncthreads_or(hi != 0u);

        // Scan idx, collect rows belonging to our 8 groups.
        if (is32) {
            const int* p = (const int*)idx_raw;
            #pragma unroll 4
            for (int i = t; i < R0; i += 256) {
                int g = p[i] - g0;
                if ((unsigned)g < GPB) {
                    int s = atomicAdd(&scnt[g], 1);
                    if (s < LCAP) slist[g * LCAP + s] = (short)i;
                }
            }
        } else {
            const long long* p = (const long long*)idx_raw;
            #pragma unroll 4
            for (int i = t; i < R0; i += 256) {
                int g = (int)p[i] - g0;
                if ((unsigned)g < GPB) {
                    int s = atomicAdd(&scnt[g], 1);
                    if (s < LCAP) slist[g * LCAP + s] = (short)i;
                }
            }
        }
        __syncthreads();

        // block-uniform prefix over 8 group counts (computed by every thread;
        // cheaper than serializing on t==0 + an extra barrier)
        int soff[GPB + 1];
        {
            int acc = 0;
            #pragma unroll
            for (int g = 0; g < GPB; g++) {
                soff[g] = acc;
                int cg = scnt[g];
                if (cg > LCAP) cg = LCAP;
                acc += cg;
                if (acc > FCAP) acc = FCAP;
            }
            soff[GPB] = acc;
        }
        // compact into flat ordered list
        #pragma unroll
        for (int g = 0; g < GPB; g++) {
            int cg = soff[g + 1] - soff[g];
            for (int s = t; s < cg; s += 256)
                sflat[soff[g] + s] = slist[g * LCAP + s];
        }
        __syncthreads();

        int total = soff[GPB];
        int gg = 0;
        int bnd = soff[1];
        float ax = 0.f, ay = 0.f, az = 0.f, aw = 0.f;   // current group sum
        float px = 0.f, py = 0.f, pz = 0.f, pw = 0.f;   // p2 partial (8 groups)
        float lsum = 0.f;                                // loss_a partial

#define FLUSH_GROUP() do {                                                   \
            float4 o_ = *(const float4*)(obs0 + (size_t)(g0 + gg) * C0 + c); \
            float dx_ = o_.x - ax, dy_ = o_.y - ay;                          \
            float dz_ = o_.z - az, dw_ = o_.w - aw;                          \
            lsum += dx_ * dx_ + dy_ * dy_ + dz_ * dz_ + dw_ * dw_;           \
            px += ax; py += ay; pz += az; pw += aw;                          \
            ax = ay = az = aw = 0.f;                                         \
        } while (0)

        for (int base = 0; base < total; base += 8) {
            float4 v[8];
            #pragma unroll
            for (int k = 0; k < 8; k++) {
                int idx = base + k;
                if (idx < total) {
                    int r = (unsigned short)sflat[idx];
                    v[k] = *(const float4*)(theta0 + (size_t)r * C0 + c);
                }
            }
            #pragma unroll
            for (int k = 0; k < 8; k++) {
                int idx = base + k;
                if (idx < total) {
                    while (idx == bnd) { FLUSH_GROUP(); gg++; bnd = soff[gg + 1]; }
                    ax += __expf(v[k].x); ay += __expf(v[k].y);
                    az += __expf(v[k].z); aw += __expf(v[k].w);
                }
            }
        }
        while (gg < GPB) { FLUSH_GROUP(); gg++; }
#undef FLUSH_GROUP

        atomicAdd(&g_p2[c + 0], px);
        atomicAdd(&g_p2[c + 1], py);
        atomicAdd(&g_p2[c + 2], pz);
        atomicAdd(&g_p2[c + 3], pw);

        float v = block_reduce256(lsum, sh);
        if (t == 0) atomicAdd(&g_loss[0], (double)v);
    } else {
        // ----------------- p1 rowsum-of-exp: one warp per theta1 row -------
        int gid = (bx >> 1) * 256 + threadIdx.x;
        int w = gid >> 5, lane = gid & 31;
        const float4* row = (const float4*)(theta1 + (size_t)w * C1);
        float s = 0.f;
        #pragma unroll 4
        for (int j = lane; j < C1 / 4; j += 32) {
            float4 v = row[j];
            s += __expf(v.x) + __expf(v.y) + __expf(v.z) + __expf(v.w);
        }
        #pragma unroll
        for (int o = 16; o; o >>= 1) s += __shfl_down_sync(0xffffffffu, s, o);
        if (lane == 0) g_p1[w] = s;
    }
}

// ---------------------------------------------------------------------------
// Epilogue (144 blocks = one wave).
//  blocks [0, C_BLOCKS): obs-C + restore g_p2.
//  blocks [C_BLOCKS, +B_BLOCKS): obs-B, FOUR mapping rows per block; p1
//    float4s loaded once per thread and reused across the 4 rows.
//  Last finisher writes the output and restores the accumulators.
// ---------------------------------------------------------------------------
__global__ __launch_bounds__(256) void k_post(const float* __restrict__ obs2,
                                              const float* __restrict__ mapping1,
                                              const float* __restrict__ obs1,
                                              float* __restrict__ out) {
    __shared__ float sh[8];
    int bx = blockIdx.x;
    int t = threadIdx.x;
    if (bx < C_BLOCKS) {
        int c = bx * 256 + t;
        float d = obs2[c] - g_p2[c];
        g_p2[c] = 0.f;                      // restore for next call
        float v = block_reduce256(d * d, sh);
        if (t == 0) atomicAdd(&g_loss[2], (double)v);
    } else {
        int w0 = (bx - C_BLOCKS) * B_ROWS_PER_BLOCK;
        const float4* p  = (const float4*)g_p1;
        const float4* m0 = (const float4*)(mapping1 + (size_t)(w0 + 0) * C0);
        const float4* m1 = (const float4*)(mapping1 + (size_t)(w0 + 1) * C0);
        const float4* m2 = (const float4*)(mapping1 + (size_t)(w0 + 2) * C0);
        const float4* m3 = (const float4*)(mapping1 + (size_t)(w0 + 3) * C0);
        float s0 = 0.f, s1 = 0.f, s2 = 0.f, s3 = 0.f;
        #pragma unroll
        for (int j = 0; j < 4; j++) {
            int k = t + j * 256;
            float4 q = p[k];
            float4 a = m0[k];
            s0 += a.x * q.x + a.y * q.y + a.z * q.z + a.w * q.w;
            float4 b = m1[k];
            s1 += b.x * q.x + b.y * q.y + b.z * q.z + b.w * q.w;
            float4 cc = m2[k];
            s2 += cc.x * q.x + cc.y * q.y + cc.z * q.z + cc.w * q.w;
            float4 dd = m3[k];
            s3 += dd.x * q.x + dd.y * q.y + dd.z * q.z + dd.w * q.w;
        }
        float r0 = block_reduce256(s0, sh); __syncthreads();
        float r1 = block_reduce256(s1, sh); __syncthreads();
        float r2 = block_reduce256(s2, sh); __syncthreads();
        float r3 = block_reduce256(s3, sh);
        if (t == 0) {
            double d0 = (double)obs1[w0 + 0] - (double)r0;
            double d1 = (double)obs1[w0 + 1] - (double)r1;
            double d2 = (double)obs1[w0 + 2] - (double)r2;
            double d3 = (double)obs1[w0 + 3] - (double)r3;
            atomicAdd(&g_loss[1], d0 * d0 + d1 * d1 + d2 * d2 + d3 * d3);
        }
    }
    __syncthreads();
    __threadfence();
    if (t == 0) {
        int done = atomicAdd(&g_done, 1);
        if (done == (int)gridDim.x - 1) {
            __threadfence();
            double la = *(volatile double*)&g_loss[0];
            double lb = *(volatile double*)&g_loss[1];
            double lc = *(volatile double*)&g_loss[2];
            la /= (double)((size_t)NG * (size_t)C0);
            lb /= (double)RM;
            lc = 0.5 * lc / (double)C0;
            out[0] = (float)((la + lb + lc) / 3.0);
            g_loss[0] = 0.0; g_loss[1] = 0.0; g_loss[2] = 0.0;
            g_done = 0;
        }
    }
}

extern "C" void kernel_launch(void* const* d_in, const int* in_sizes, int n_in,
                              void* d_out, int out_size) {
    const float* theta0   = (const float*)d_in[0];
    const float* theta1   = (const float*)d_in[1];
    const float* obs0     = (const float*)d_in[2];
    const float* obs1     = (const float*)d_in[3];
    const float* obs2     = (const float*)d_in[4];
    const void*  idx0     = d_in[5];
    const float* mapping1 = (const float*)d_in[6];
    float* out = (float*)d_out;

    k_main<<<A_BLOCKS + P1_BLOCKS, 256>>>(theta0, obs0, theta1,
                                          (const unsigned int*)idx0);
    k_post<<<C_BLOCKS + B_BLOCKS, 256>>>(obs2, mapping1, obs1, out);
}